// round 16
// baseline (speedup 1.0000x reference)
#include <cuda_runtime.h>
#include <cuda_fp16.h>
#include <cstdint>

// Capsule layer, three-kernel split (R15 = R14 + conv A-frag LDS.64):
//   prep:  permute W into fp16 m16n8k16 fragment layout (coalesced via smem)
//   conv:  fp16 mma.sync m16n8k16 GEMM votes[i][128px,128cf]; fp32 acc,
//          fp16 vote store; 512 thr, warp tile M32xN32, 2 blocks/SM.
//          R15: x tile stored with interleaved fin-pair order (0,4,1,5,2,6,3,7)
//          so each A-fragment fetch is LDS.64 (pairs c4 / c4+4 adjacent):
//          8 LDS.32 -> 4 LDS.64 per kk step.
//   routing: fp32 dynamic routing, one warp per pixel (R14 distributed form).
//
//   x [32,32,32,8,16] f32   W [8,3,3,16,128] f32   b [1,1,8,16] f32
//   out [32,32,32,8,16] f32

#define EPS_SQ 1e-7f

__device__ __half   g_votes[32768 * 1024];          // [px][i*128+cf] fp16
__device__ uint2    g_Wfrag[8 * 9 * 16 * 32];       // fp16 B fragments

__device__ __forceinline__ void mma16(float c[4], const uint4& a, const uint2& b) {
    asm volatile(
        "mma.sync.aligned.m16n8k16.row.col.f32.f16.f16.f32 "
        "{%0,%1,%2,%3}, {%4,%5,%6,%7}, {%8,%9}, {%0,%1,%2,%3};"
        : "+f"(c[0]), "+f"(c[1]), "+f"(c[2]), "+f"(c[3])
        : "r"(a.x), "r"(a.y), "r"(a.z), "r"(a.w), "r"(b.x), "r"(b.y));
}
__device__ __forceinline__ uint32_t h2u(__half2 h) {
    return *reinterpret_cast<uint32_t*>(&h);
}

// B fragments: [r = i*9+kk][nt(16)][lane(32)] uint2.
__global__ void prep_weights(const float* __restrict__ W) {
    __shared__ float sW[2048];                    // [fin 16][cf 128]
    const int r = blockIdx.x, t = threadIdx.x;
    const float4* Wg = reinterpret_cast<const float4*>(W) + r * 512;
    reinterpret_cast<float4*>(sW)[t]       = Wg[t];
    reinterpret_cast<float4*>(sW)[t + 256] = Wg[t + 256];
    __syncthreads();
    #pragma unroll
    for (int j = 0; j < 2; j++) {
        int fr = t + j * 256;                     // 0..511
        int lane = fr & 31, nt = fr >> 5;
        int g = lane >> 2, c4 = lane & 3;
        int cf = nt * 8 + g;
        const float* p = sW + cf;
        uint2 o;
        o.x = h2u(__floats2half2_rn(p[(2 * c4) * 128],     p[(2 * c4 + 1) * 128]));
        o.y = h2u(__floats2half2_rn(p[(2 * c4 + 8) * 128], p[(2 * c4 + 9) * 128]));
        g_Wfrag[r * 512 + fr] = o;
    }
}

// ---- K1: conv votes GEMM. grid (256 m-blocks, 8 i), 512 threads ----
// Block = 128 px (4 h-rows x 32 w of batch mblk>>3), 128 cf, one capsule i.
// 16 warps: wm = wid&3 (h-row, M32), wn = wid>>2 (N32 = 4 n8 tiles).
// x_h layout: [pix(204)][pos(8)] u32(half2 of fins), pos = interleaved
// fin-pair order: pos(fp) = (fp&3)*2 + (fp>>2)  (pairs fp, fp+4 adjacent).
__global__ __launch_bounds__(512, 2)
void conv_votes_kernel(const float* __restrict__ x)
{
    __shared__ uint32_t x_h[204 * 8];        // 6528 B
    __shared__ uint2    s_w[9 * 16 * 32];    // W frags for this i (36 KB)

    const int t = threadIdx.x, lane = t & 31, wid = t >> 5;
    const int mblk = blockIdx.x, i = blockIdx.y;
    const int b = mblk >> 3, h0 = (mblk & 7) << 2;

    // stage W fragments: 2304 uint4
    {
        const uint4* gw4 = reinterpret_cast<const uint4*>(g_Wfrag) + i * 2304;
        uint4* sw4 = reinterpret_cast<uint4*>(s_w);
        #pragma unroll
        for (int j = t; j < 2304; j += 512)
            sw4[j] = gw4[j];
    }

    // x tile (6 rows x 34 cols x 16 fin) -> packed half2, interleaved pos
    for (int e4 = t; e4 < 816; e4 += 512) {
        int pix = e4 >> 2, q = e4 & 3;       // q covers fin 4q..4q+3
        int r = pix / 34, c = pix - r * 34;
        int hh = h0 + r - 1, ww = c - 1;
        float4 v = make_float4(0.f, 0.f, 0.f, 0.f);
        if (hh >= 0 && hh < 32 && ww >= 0 && ww < 32)
            v = reinterpret_cast<const float4*>(x)
                  [((b * 32 + hh) * 32 + ww) * 32 + i * 4 + q];
        // fin pairs fp = 2q, 2q+1 -> positions (fp&3)*2 + (fp>>2)
        int pos0 = ((2 * q) & 3) * 2 + ((2 * q) >> 2);
        int pos1 = ((2 * q + 1) & 3) * 2 + ((2 * q + 1) >> 2);
        x_h[pix * 8 + pos0] = h2u(__floats2half2_rn(v.x, v.y));
        x_h[pix * 8 + pos1] = h2u(__floats2half2_rn(v.z, v.w));
    }
    __syncthreads();

    const int g = lane >> 2, c4 = lane & 3;
    const int wm = wid & 3, wn = wid >> 2;

    float acc[2][4][4];
    #pragma unroll
    for (int mt = 0; mt < 2; mt++)
        #pragma unroll
        for (int n = 0; n < 4; n++)
            #pragma unroll
            for (int j = 0; j < 4; j++) acc[mt][n][j] = 0.f;

    const uint2* x_h2 = reinterpret_cast<const uint2*>(x_h);  // [pix*4 + c4]

    #pragma unroll
    for (int kk = 0; kk < 9; kk++) {
        const int ky = kk / 3, kx = kk - ky * 3;
        const int pbase = (wm + ky) * 34 + kx + g;
        uint4 a[2];
        #pragma unroll
        for (int mt = 0; mt < 2; mt++) {
            const int p0 = pbase + mt * 16;
            // pos 2c4 = fin pair c4 (A0/A1), pos 2c4+1 = fin pair c4+4 (A2/A3)
            uint2 r0 = x_h2[p0 * 4 + c4];          // px p0:  (A0, A2)
            uint2 r1 = x_h2[(p0 + 8) * 4 + c4];    // px p0+8:(A1, A3)
            a[mt].x = r0.x;
            a[mt].y = r1.x;
            a[mt].z = r0.y;
            a[mt].w = r1.y;
        }
        #pragma unroll
        for (int n = 0; n < 4; n++) {
            uint2 bb = s_w[(kk * 16 + wn * 4 + n) * 32 + lane];
            mma16(acc[0][n], a[0], bb);
            mma16(acc[1][n], a[1], bb);
        }
    }

    // store votes fp16: u32 idx = px*512 + i*64 + (wn*4+n)*4 + c4
    uint32_t* vp = reinterpret_cast<uint32_t*>(g_votes) +
                   (size_t)(mblk * 128) * 512 + i * 64 + wn * 16 + c4;
    #pragma unroll
    for (int mt = 0; mt < 2; mt++) {
        const int m0 = wm * 32 + mt * 16 + g;
        #pragma unroll
        for (int n = 0; n < 4; n++) {
            vp[(size_t)m0 * 512 + n * 4] =
                h2u(__floats2half2_rn(acc[mt][n][0], acc[mt][n][1]));
            vp[(size_t)(m0 + 8) * 512 + n * 4] =
                h2u(__floats2half2_rn(acc[mt][n][2], acc[mt][n][3]));
        }
    }
}

// ---- K2: routing. grid 4096, 256 threads; warp w routes px = blk*8+w ----
// lane = c*4 + fq. Lane owns logits for capsules i = 2fq, 2fq+1 (A, B).
__global__ __launch_bounds__(256)
void routing_kernel(const float* __restrict__ bias, float* __restrict__ out)
{
    const int t = threadIdx.x, lane = t & 31, wid = t >> 5;
    const int px = blockIdx.x * 8 + wid;
    const bool b0 = (lane & 1) != 0;     // fq bit0
    const bool b1 = (lane & 2) != 0;     // fq bit1

    const float4 bv = reinterpret_cast<const float4*>(bias)[lane];
    const uint2* vg = reinterpret_cast<const uint2*>(g_votes) + (size_t)px * 256;

    float4 v[8];
    #pragma unroll
    for (int i = 0; i < 8; i++) {
        uint2 raw = vg[i * 32 + lane];
        float2 f01 = __half22float2(*reinterpret_cast<__half2*>(&raw.x));
        float2 f23 = __half22float2(*reinterpret_cast<__half2*>(&raw.y));
        v[i] = make_float4(f01.x, f01.y, f23.x, f23.y);
    }

    float logitA = 0.f, logitB = 0.f;    // i = 2fq, 2fq+1
    float4 act = make_float4(0.f, 0.f, 0.f, 0.f);
    float route[8];

    #pragma unroll
    for (int r = 0; r < 3; r++) {
        if (r == 0) {
            #pragma unroll
            for (int i = 0; i < 8; i++) route[i] = 0.125f;   // softmax(0)
        } else {
            // distributed softmax (no max-sub; |logit| <~ 20, fp32-safe)
            float eA = __expf(logitA), eB = __expf(logitB);
            float sA = eA, sB = eB;
            sA += __shfl_xor_sync(0xffffffffu, sA, 4);
            sA += __shfl_xor_sync(0xffffffffu, sA, 8);
            sA += __shfl_xor_sync(0xffffffffu, sA, 16);
            sB += __shfl_xor_sync(0xffffffffu, sB, 4);
            sB += __shfl_xor_sync(0xffffffffu, sB, 8);
            sB += __shfl_xor_sync(0xffffffffu, sB, 16);
            float rA = __fdividef(eA, sA);   // route[2fq]
            float rB = __fdividef(eB, sB);   // route[2fq+1]
            // all-gather route[0..7]: xor1 then xor2 over fq bits
            float pA = __shfl_xor_sync(0xffffffffu, rA, 1);
            float pB = __shfl_xor_sync(0xffffffffu, rB, 1);
            float x0 = b0 ? pA : rA, x1 = b0 ? pB : rB;
            float x2 = b0 ? rA : pA, x3 = b0 ? rB : pB;
            float y0 = __shfl_xor_sync(0xffffffffu, x0, 2);
            float y1 = __shfl_xor_sync(0xffffffffu, x1, 2);
            float y2 = __shfl_xor_sync(0xffffffffu, x2, 2);
            float y3 = __shfl_xor_sync(0xffffffffu, x3, 2);
            route[0] = b1 ? y0 : x0;  route[1] = b1 ? y1 : x1;
            route[2] = b1 ? y2 : x2;  route[3] = b1 ? y3 : x3;
            route[4] = b1 ? x0 : y0;  route[5] = b1 ? x1 : y1;
            route[6] = b1 ? x2 : y2;  route[7] = b1 ? x3 : y3;
        }
        float4 pre = bv;
        #pragma unroll
        for (int i = 0; i < 8; i++) {
            pre.x += route[i] * v[i].x;
            pre.y += route[i] * v[i].y;
            pre.z += route[i] * v[i].z;
            pre.w += route[i] * v[i].w;
        }
        float s2 = pre.x * pre.x + pre.y * pre.y + pre.z * pre.z + pre.w * pre.w;
        s2 += __shfl_xor_sync(0xffffffffu, s2, 1);
        s2 += __shfl_xor_sync(0xffffffffu, s2, 2);
        float scale = s2 / (1.f + s2) * rsqrtf(s2 + EPS_SQ);
        act.x = scale * pre.x;
        act.y = scale * pre.y;
        act.z = scale * pre.z;
        act.w = scale * pre.w;
        if (r < 2) {
            // agreement partials (own 4 f's), then reduce-scatter over fq
            float p[8];
            #pragma unroll
            for (int i = 0; i < 8; i++)
                p[i] = v[i].x * act.x + v[i].y * act.y +
                       v[i].z * act.z + v[i].w * act.w;
            float s0 = b0 ? p[0] : p[2];
            float s1 = b0 ? p[1] : p[3];
            float s2a = b0 ? p[4] : p[6];
            float s3 = b0 ? p[5] : p[7];
            float q0 = __shfl_xor_sync(0xffffffffu, s0, 1);
            float q1 = __shfl_xor_sync(0xffffffffu, s1, 1);
            float q2 = __shfl_xor_sync(0xffffffffu, s2a, 1);
            float q3 = __shfl_xor_sync(0xffffffffu, s3, 1);
            float u0 = (b0 ? p[2] : p[0]) + q0;
            float u1 = (b0 ? p[3] : p[1]) + q1;
            float u2 = (b0 ? p[6] : p[4]) + q2;
            float u3 = (b0 ? p[7] : p[5]) + q3;
            float sa = b1 ? u0 : u2;
            float sb = b1 ? u1 : u3;
            float qa = __shfl_xor_sync(0xffffffffu, sa, 2);
            float qb = __shfl_xor_sync(0xffffffffu, sb, 2);
            logitA += (b1 ? u2 : u0) + qa;
            logitB += (b1 ? u3 : u1) + qb;
        }
    }

    reinterpret_cast<float4*>(out)[(size_t)px * 32 + lane] = act;
}

extern "C" void kernel_launch(void* const* d_in, const int* in_sizes, int n_in,
                              void* d_out, int out_size)
{
    const float* x    = (const float*)d_in[0];
    const float* Wt   = (const float*)d_in[1];
    const float* bias = (const float*)d_in[2];
    float* out = (float*)d_out;
    (void)in_sizes; (void)n_in; (void)out_size;

    prep_weights<<<72, 256>>>(Wt);
    dim3 gridA(256, 8);
    conv_votes_kernel<<<gridA, 512>>>(x);
    routing_kernel<<<4096, 256>>>(bias, out);
}